// round 7
// baseline (speedup 1.0000x reference)
#include <cuda_runtime.h>
#include <cuda_bf16.h>
#include <math.h>

// ---------------------------------------------------------------------------
// GCN via CSR built from deg-pass slot returns (no cursor atomics):
//   degslot: slot[e] = atomicAdd(deg[dst[e]],1)   (one RMW pass, slot saved)
//   scan(deg) -> rowptr ; scan3 also computes dinv, y = dinv*x
//   fill: csr[rowptr[dst]+slot] = src             (gather + store, no atomics)
//   gather1 (4 lanes/node): S=y[i]+Sum y[nbr]; h1=relu(dinv*S@W1+b1); B=dinv*(h1@W2)
//   gather2 (4 lanes/node): T=B[i]+Sum B[nbr]; sigmoid(dinv*T+b2); MLP head -> out
// ---------------------------------------------------------------------------

#define MAX_N 1000000
#define MAX_E 16000000
#define NTHREADS 256
#define SCAN_T 256
#define SCAN_I 8
#define SCAN_TILE (SCAN_T * SCAN_I)   // 2048

__device__ int    g_deg[MAX_N];
__device__ int    g_rowptr[MAX_N + 1];
__device__ int    g_slot[MAX_E];
__device__ int    g_csr[MAX_E];
__device__ int    g_bsum[1024];
__device__ float  g_dinv[MAX_N];
__device__ float2 g_y[MAX_N];      // layer-1 gather source (dinv*x)
__device__ float4 g_featB[MAX_N];  // layer-2 gather source (dinv*(h1@W2), w=0)

// ---- deg + slot: slot[e] = old count of dst ----
__global__ void k_degslot(const int* __restrict__ dst, int* __restrict__ slot, int E) {
    int i = (blockIdx.x * blockDim.x + threadIdx.x) * 4;
    if (i + 3 < E) {
        int4 d = *(const int4*)(dst + i);
        int4 s;
        s.x = atomicAdd(&g_deg[d.x], 1);
        s.y = atomicAdd(&g_deg[d.y], 1);
        s.z = atomicAdd(&g_deg[d.z], 1);
        s.w = atomicAdd(&g_deg[d.w], 1);
        *(int4*)(slot + i) = s;
    } else {
        for (int j = i; j < E; j++) slot[j] = atomicAdd(&g_deg[dst[j]], 1);
    }
}

// ---- exclusive scan of deg -> rowptr (3 kernels; validated in R3) ----
__global__ void k_scan1(int N) {
    __shared__ int wsum[SCAN_T / 32];
    int t = threadIdx.x;
    int base = blockIdx.x * SCAN_TILE + t * SCAN_I;
    int v[SCAN_I];
#pragma unroll
    for (int k = 0; k < SCAN_I; k++) { int idx = base + k; v[k] = (idx < N) ? g_deg[idx] : 0; }
    int tot = 0;
#pragma unroll
    for (int k = 0; k < SCAN_I; k++) { int t0 = v[k]; v[k] = tot; tot += t0; }
    int lane = t & 31, wid = t >> 5;
    int x = tot;
    for (int d = 1; d < 32; d <<= 1) { int y = __shfl_up_sync(0xffffffffu, x, d); if (lane >= d) x += y; }
    int wexcl = x - tot;
    if (lane == 31) wsum[wid] = x;
    __syncthreads();
    if (wid == 0) {
        int s = (lane < SCAN_T / 32) ? wsum[lane] : 0;
        int xs = s;
        for (int d = 1; d < 32; d <<= 1) { int y = __shfl_up_sync(0xffffffffu, xs, d); if (lane >= d) xs += y; }
        if (lane < SCAN_T / 32) wsum[lane] = xs - s;
    }
    __syncthreads();
    int off = wexcl + wsum[wid];
#pragma unroll
    for (int k = 0; k < SCAN_I; k++) { int idx = base + k; if (idx < N) g_rowptr[idx] = off + v[k]; }
    if (t == SCAN_T - 1) g_bsum[blockIdx.x] = off + tot;
}

__global__ void k_scan2(int nblk) {
    __shared__ int sh[1024];
    int t = threadIdx.x;
    int v = (t < nblk) ? g_bsum[t] : 0;
    sh[t] = v;
    __syncthreads();
    for (int d = 1; d < 1024; d <<= 1) {
        int y = (t >= d) ? sh[t - d] : 0;
        __syncthreads();
        sh[t] += y;
        __syncthreads();
    }
    if (t < nblk) g_bsum[t] = sh[t] - v;
}

// ---- scan3 + node1 fused: finalize rowptr; dinv = rsqrt(deg+1); y = dinv*x ----
__global__ void k_scan3(const float* __restrict__ x, int N, int E) {
    int i = blockIdx.x * blockDim.x + threadIdx.x;
    if (i < N) {
        int r = g_rowptr[i] + g_bsum[i / SCAN_TILE];
        g_rowptr[i] = r;
        float dinv = rsqrtf((float)(g_deg[i] + 1));
        float2 xv = ((const float2*)x)[i];
        float2 y;
        y.x = dinv * xv.x;
        y.y = dinv * xv.y;
        g_dinv[i] = dinv;
        g_y[i]    = y;
    }
    if (i == 0) g_rowptr[N] = E;
}

// ---- CSR fill (atomic-free): csr[rowptr[dst]+slot] = src ----
__global__ void k_fill(const int* __restrict__ src, const int* __restrict__ dst,
                       const int* __restrict__ slot, int E) {
    int i = (blockIdx.x * blockDim.x + threadIdx.x) * 4;
    if (i + 3 < E) {
        int4 s  = *(const int4*)(src + i);
        int4 d  = *(const int4*)(dst + i);
        int4 sl = *(const int4*)(slot + i);
        g_csr[g_rowptr[d.x] + sl.x] = s.x;
        g_csr[g_rowptr[d.y] + sl.y] = s.y;
        g_csr[g_rowptr[d.z] + sl.z] = s.z;
        g_csr[g_rowptr[d.w] + sl.w] = s.w;
    } else {
        for (int j = i; j < E; j++) g_csr[g_rowptr[dst[j]] + slot[j]] = src[j];
    }
}

// ---- gather layer 1 (4 lanes per node) + fused node2 ----
__global__ void k_gather1(const float* __restrict__ W1, const float* __restrict__ b1,
                          const float* __restrict__ W2, int N) {
    int gt   = blockIdx.x * blockDim.x + threadIdx.x;
    int node = gt >> 2;
    int lane = gt & 3;
    if (node >= N) return;
    int start = g_rowptr[node];
    int end   = g_rowptr[node + 1];
    float sx = 0.f, sy = 0.f;
    for (int j = start + lane; j < end; j += 4) {
        float2 f = g_y[g_csr[j]];
        sx += f.x; sy += f.y;
    }
    // reduce across the 4-lane group
    sx += __shfl_xor_sync(0xffffffffu, sx, 1);
    sy += __shfl_xor_sync(0xffffffffu, sy, 1);
    sx += __shfl_xor_sync(0xffffffffu, sx, 2);
    sy += __shfl_xor_sync(0xffffffffu, sy, 2);
    if (lane == 0) {
        float dinv = g_dinv[node];
        float2 self = g_y[node];
        sx += self.x; sy += self.y;
        // h1 = relu(dinv*(S@W1) + b1); W1 [2,4] row-major
        float h0 = fmaxf(dinv * (sx * __ldg(W1+0) + sy * __ldg(W1+4)) + __ldg(b1+0), 0.f);
        float h1 = fmaxf(dinv * (sx * __ldg(W1+1) + sy * __ldg(W1+5)) + __ldg(b1+1), 0.f);
        float h2 = fmaxf(dinv * (sx * __ldg(W1+2) + sy * __ldg(W1+6)) + __ldg(b1+2), 0.f);
        float h3 = fmaxf(dinv * (sx * __ldg(W1+3) + sy * __ldg(W1+7)) + __ldg(b1+3), 0.f);
        // featB = dinv*(h1@W2); W2 [4,3] row-major
        float4 g;
        g.x = dinv * (h0*__ldg(W2+0) + h1*__ldg(W2+3) + h2*__ldg(W2+6) + h3*__ldg(W2+9));
        g.y = dinv * (h0*__ldg(W2+1) + h1*__ldg(W2+4) + h2*__ldg(W2+7) + h3*__ldg(W2+10));
        g.z = dinv * (h0*__ldg(W2+2) + h1*__ldg(W2+5) + h2*__ldg(W2+8) + h3*__ldg(W2+11));
        g.w = 0.f;
        g_featB[node] = g;
    }
}

// ---- gather layer 2 (4 lanes per node) + fused node3 / MLP head ----
__global__ void k_gather2(const float* __restrict__ b2,
                          const float* __restrict__ W3, const float* __restrict__ b3,
                          const float* __restrict__ W4, const float* __restrict__ b4,
                          const float* __restrict__ W5, const float* __restrict__ b5,
                          float* __restrict__ out, int N) {
    int gt   = blockIdx.x * blockDim.x + threadIdx.x;
    int node = gt >> 2;
    int lane = gt & 3;
    if (node >= N) return;
    int start = g_rowptr[node];
    int end   = g_rowptr[node + 1];
    float sx = 0.f, sy = 0.f, sz = 0.f;
    for (int j = start + lane; j < end; j += 4) {
        float4 f = g_featB[g_csr[j]];
        sx += f.x; sy += f.y; sz += f.z;
    }
    sx += __shfl_xor_sync(0xffffffffu, sx, 1);
    sy += __shfl_xor_sync(0xffffffffu, sy, 1);
    sz += __shfl_xor_sync(0xffffffffu, sz, 1);
    sx += __shfl_xor_sync(0xffffffffu, sx, 2);
    sy += __shfl_xor_sync(0xffffffffu, sy, 2);
    sz += __shfl_xor_sync(0xffffffffu, sz, 2);
    if (lane == 0) {
        float dinv = g_dinv[node];
        float4 self = g_featB[node];
        sx += self.x; sy += self.y; sz += self.z;
        float q0 = 1.f / (1.f + expf(-(sx * dinv + __ldg(b2+0))));
        float q1 = 1.f / (1.f + expf(-(sy * dinv + __ldg(b2+1))));
        float q2 = 1.f / (1.f + expf(-(sz * dinv + __ldg(b2+2))));
        // h3 = relu(q @ W3[3,4] + b3)
        float u0 = fmaxf(q0*__ldg(W3+0) + q1*__ldg(W3+4) + q2*__ldg(W3+8)  + __ldg(b3+0), 0.f);
        float u1 = fmaxf(q0*__ldg(W3+1) + q1*__ldg(W3+5) + q2*__ldg(W3+9)  + __ldg(b3+1), 0.f);
        float u2 = fmaxf(q0*__ldg(W3+2) + q1*__ldg(W3+6) + q2*__ldg(W3+10) + __ldg(b3+2), 0.f);
        float u3 = fmaxf(q0*__ldg(W3+3) + q1*__ldg(W3+7) + q2*__ldg(W3+11) + __ldg(b3+3), 0.f);
        // h4 = relu(u @ W4[4,3] + b4)
        float v0 = fmaxf(u0*__ldg(W4+0) + u1*__ldg(W4+3) + u2*__ldg(W4+6) + u3*__ldg(W4+9)  + __ldg(b4+0), 0.f);
        float v1 = fmaxf(u0*__ldg(W4+1) + u1*__ldg(W4+4) + u2*__ldg(W4+7) + u3*__ldg(W4+10) + __ldg(b4+1), 0.f);
        float v2 = fmaxf(u0*__ldg(W4+2) + u1*__ldg(W4+5) + u2*__ldg(W4+8) + u3*__ldg(W4+11) + __ldg(b4+2), 0.f);
        out[node] = v0*__ldg(W5+0) + v1*__ldg(W5+1) + v2*__ldg(W5+2) + __ldg(b5+0);
    }
}

extern "C" void kernel_launch(void* const* d_in, const int* in_sizes, int n_in,
                              void* d_out, int out_size) {
    const float* x    = (const float*)d_in[0];
    const int*   eidx = (const int*)d_in[1];
    int N = in_sizes[0] / 2;
    int E = in_sizes[1] / 2;
    const int* src = eidx;
    const int* dst = eidx + E;
    float* out = (float*)d_out;

    const float* W1 = (const float*)d_in[2];
    const float* b1 = (const float*)d_in[3];
    const float* W2 = (const float*)d_in[4];
    const float* b2 = (const float*)d_in[5];
    const float* W3 = (const float*)d_in[6];
    const float* b3 = (const float*)d_in[7];
    const float* W4 = (const float*)d_in[8];
    const float* b4 = (const float*)d_in[9];
    const float* W5 = (const float*)d_in[10];
    const float* b5 = (const float*)d_in[11];

    void* degPtr = nullptr;
    cudaGetSymbolAddress(&degPtr, g_deg);
    cudaMemsetAsync(degPtr, 0, N * sizeof(int), 0);

    int* slotPtr = nullptr;
    cudaGetSymbolAddress((void**)&slotPtr, g_slot);

    int nodeBlocks   = (N + NTHREADS - 1) / NTHREADS;
    int edgeBlocks   = ((E + 3) / 4 + NTHREADS - 1) / NTHREADS;
    int scanBlocks   = (N + SCAN_TILE - 1) / SCAN_TILE;
    int gatherBlocks = ((N * 4) + NTHREADS - 1) / NTHREADS;

    k_degslot<<<edgeBlocks, NTHREADS>>>(dst, slotPtr, E);
    k_scan1  <<<scanBlocks, SCAN_T>>>(N);
    k_scan2  <<<1, 1024>>>(scanBlocks);
    k_scan3  <<<nodeBlocks, NTHREADS>>>(x, N, E);
    k_fill   <<<edgeBlocks, NTHREADS>>>(src, dst, slotPtr, E);
    k_gather1<<<gatherBlocks, NTHREADS>>>(W1, b1, W2, N);
    k_gather2<<<gatherBlocks, NTHREADS>>>(b2, W3, b3, W4, b4, W5, b5, out, N);
}

// round 11
// speedup vs baseline: 1.3118x; 1.3118x over previous
#include <cuda_runtime.h>
#include <cuda_bf16.h>
#include <math.h>

// ---------------------------------------------------------------------------
// GCN, RED-scatter formulation (R4 structure) with 8-edges/thread MLP batching:
//   deg -> node1 (y = dinv*x, float2) -> scatter1 (red.v2)
//       -> node2 (h1 = relu(dinv*(S@W1)+b1); featB = dinv*(h1@W2)) -> scatter2 (red.v4)
//       -> node3 (sigmoid + MLP head)
// gcnconv: out[d] = dinv[d] * ( sum_{s in N(d)} g[s] + g[d] ),  dinv = rsqrt(deg+1)
// ---------------------------------------------------------------------------

#define MAX_N 1000000
#define NTHREADS 256

__device__ int    g_deg[MAX_N];
__device__ float  g_dinv[MAX_N];
__device__ float2 g_y[MAX_N];      // layer-1 gather source (dinv * x), 8B
__device__ float2 g_accA[MAX_N];   // layer-1 accumulator
__device__ float4 g_featB[MAX_N];  // layer-2 gather source (dinv * h1@W2, w=0)
__device__ float4 g_accB[MAX_N];   // layer-2 accumulator

// packed weights in constant memory
// W1:0(8) b1:8(4) W2:12(12) b2:24(3) W3:27(12) b3:39(4) W4:43(12) b4:55(3) W5:58(3) b5:61(1)
__constant__ float cW[64];

__device__ __forceinline__ void red2(float2* p, float2 v) {
    asm volatile("red.global.add.v2.f32 [%0], {%1,%2};"
                 :: "l"(p), "f"(v.x), "f"(v.y) : "memory");
}
__device__ __forceinline__ void red4(float4* p, float4 v) {
    asm volatile("red.global.add.v4.f32 [%0], {%1,%2,%3,%4};"
                 :: "l"(p), "f"(v.x), "f"(v.y), "f"(v.z), "f"(v.w) : "memory");
}

// ---- degree count: 8 edges/thread ----
__global__ void k_deg(const int* __restrict__ dst, int E) {
    int i = (blockIdx.x * blockDim.x + threadIdx.x) * 8;
    if (i + 7 < E) {
        int4 d0 = *(const int4*)(dst + i);
        int4 d1 = *(const int4*)(dst + i + 4);
        atomicAdd(&g_deg[d0.x], 1);
        atomicAdd(&g_deg[d0.y], 1);
        atomicAdd(&g_deg[d0.z], 1);
        atomicAdd(&g_deg[d0.w], 1);
        atomicAdd(&g_deg[d1.x], 1);
        atomicAdd(&g_deg[d1.y], 1);
        atomicAdd(&g_deg[d1.z], 1);
        atomicAdd(&g_deg[d1.w], 1);
    } else {
        for (int j = i; j < E; j++) atomicAdd(&g_deg[dst[j]], 1);
    }
}

// ---- node pass 1: dinv, y = dinv * x, accA = y (self loop) ----
__global__ void k_node1(const float* __restrict__ x, int N) {
    int i = blockIdx.x * blockDim.x + threadIdx.x;
    if (i >= N) return;
    float dinv = rsqrtf((float)(g_deg[i] + 1));
    float2 xv = ((const float2*)x)[i];
    float2 y;
    y.x = dinv * xv.x;
    y.y = dinv * xv.y;
    g_dinv[i] = dinv;
    g_y[i]    = y;
    g_accA[i] = y;
}

// ---- scatter layer 1: accA[dst] += y[src]  (red.v2, 8 edges/thread) ----
__global__ void k_scatter1(const int* __restrict__ src, const int* __restrict__ dst, int E) {
    int i = (blockIdx.x * blockDim.x + threadIdx.x) * 8;
    if (i + 7 < E) {
        int4 s0 = *(const int4*)(src + i);
        int4 s1 = *(const int4*)(src + i + 4);
        int4 d0 = *(const int4*)(dst + i);
        int4 d1 = *(const int4*)(dst + i + 4);
        float2 a0 = __ldg(&g_y[s0.x]);
        float2 a1 = __ldg(&g_y[s0.y]);
        float2 a2 = __ldg(&g_y[s0.z]);
        float2 a3 = __ldg(&g_y[s0.w]);
        float2 a4 = __ldg(&g_y[s1.x]);
        float2 a5 = __ldg(&g_y[s1.y]);
        float2 a6 = __ldg(&g_y[s1.z]);
        float2 a7 = __ldg(&g_y[s1.w]);
        red2(&g_accA[d0.x], a0);
        red2(&g_accA[d0.y], a1);
        red2(&g_accA[d0.z], a2);
        red2(&g_accA[d0.w], a3);
        red2(&g_accA[d1.x], a4);
        red2(&g_accA[d1.y], a5);
        red2(&g_accA[d1.z], a6);
        red2(&g_accA[d1.w], a7);
    } else {
        for (int j = i; j < E; j++) red2(&g_accA[dst[j]], g_y[src[j]]);
    }
}

// ---- node pass 2: h1 = relu(dinv*(S@W1)+b1); featB = dinv*(h1@W2); accB = featB ----
__global__ void k_node2(int N) {
    int i = blockIdx.x * blockDim.x + threadIdx.x;
    if (i >= N) return;
    float dinv = g_dinv[i];
    float2 S = g_accA[i];
    // W1 [2,4] row-major at cW[0..7], b1 at cW[8..11]
    float h0 = fmaxf(dinv * (S.x * cW[0] + S.y * cW[4]) + cW[8],  0.0f);
    float h1 = fmaxf(dinv * (S.x * cW[1] + S.y * cW[5]) + cW[9],  0.0f);
    float h2 = fmaxf(dinv * (S.x * cW[2] + S.y * cW[6]) + cW[10], 0.0f);
    float h3 = fmaxf(dinv * (S.x * cW[3] + S.y * cW[7]) + cW[11], 0.0f);
    // W2 [4,3] row-major at cW[12..23]
    float4 g;
    g.x = dinv * (h0 * cW[12] + h1 * cW[15] + h2 * cW[18] + h3 * cW[21]);
    g.y = dinv * (h0 * cW[13] + h1 * cW[16] + h2 * cW[19] + h3 * cW[22]);
    g.z = dinv * (h0 * cW[14] + h1 * cW[17] + h2 * cW[20] + h3 * cW[23]);
    g.w = 0.0f;
    g_featB[i] = g;
    g_accB[i]  = g;
}

// ---- scatter layer 2: accB[dst] += featB[src]  (red.v4, 8 edges/thread) ----
__global__ void k_scatter2(const int* __restrict__ src, const int* __restrict__ dst, int E) {
    int i = (blockIdx.x * blockDim.x + threadIdx.x) * 8;
    if (i + 7 < E) {
        int4 s0 = *(const int4*)(src + i);
        int4 s1 = *(const int4*)(src + i + 4);
        int4 d0 = *(const int4*)(dst + i);
        int4 d1 = *(const int4*)(dst + i + 4);
        float4 a0 = __ldg(&g_featB[s0.x]);
        float4 a1 = __ldg(&g_featB[s0.y]);
        float4 a2 = __ldg(&g_featB[s0.z]);
        float4 a3 = __ldg(&g_featB[s0.w]);
        float4 a4 = __ldg(&g_featB[s1.x]);
        float4 a5 = __ldg(&g_featB[s1.y]);
        float4 a6 = __ldg(&g_featB[s1.z]);
        float4 a7 = __ldg(&g_featB[s1.w]);
        red4(&g_accB[d0.x], a0);
        red4(&g_accB[d0.y], a1);
        red4(&g_accB[d0.z], a2);
        red4(&g_accB[d0.w], a3);
        red4(&g_accB[d1.x], a4);
        red4(&g_accB[d1.y], a5);
        red4(&g_accB[d1.z], a6);
        red4(&g_accB[d1.w], a7);
    } else {
        for (int j = i; j < E; j++) red4(&g_accB[dst[j]], g_featB[src[j]]);
    }
}

// ---- node pass 3: sigmoid + MLP head ----
__global__ void k_node3(float* __restrict__ out, int N) {
    int i = blockIdx.x * blockDim.x + threadIdx.x;
    if (i >= N) return;
    float dinv = g_dinv[i];
    float4 a = g_accB[i];
    float q0 = 1.0f / (1.0f + expf(-(a.x * dinv + cW[24])));
    float q1 = 1.0f / (1.0f + expf(-(a.y * dinv + cW[25])));
    float q2 = 1.0f / (1.0f + expf(-(a.z * dinv + cW[26])));
    // h3 = relu(q @ W3[3,4] + b3), W3 at 27, b3 at 39
    float u0 = fmaxf(q0 * cW[27] + q1 * cW[31] + q2 * cW[35] + cW[39], 0.0f);
    float u1 = fmaxf(q0 * cW[28] + q1 * cW[32] + q2 * cW[36] + cW[40], 0.0f);
    float u2 = fmaxf(q0 * cW[29] + q1 * cW[33] + q2 * cW[37] + cW[41], 0.0f);
    float u3 = fmaxf(q0 * cW[30] + q1 * cW[34] + q2 * cW[38] + cW[42], 0.0f);
    // h4 = relu(u @ W4[4,3] + b4), W4 at 43, b4 at 55
    float v0 = fmaxf(u0 * cW[43] + u1 * cW[46] + u2 * cW[49] + u3 * cW[52] + cW[55], 0.0f);
    float v1 = fmaxf(u0 * cW[44] + u1 * cW[47] + u2 * cW[50] + u3 * cW[53] + cW[56], 0.0f);
    float v2 = fmaxf(u0 * cW[45] + u1 * cW[48] + u2 * cW[51] + u3 * cW[54] + cW[57], 0.0f);
    out[i] = v0 * cW[58] + v1 * cW[59] + v2 * cW[60] + cW[61];
}

extern "C" void kernel_launch(void* const* d_in, const int* in_sizes, int n_in,
                              void* d_out, int out_size) {
    const float* x    = (const float*)d_in[0];
    const int*   eidx = (const int*)d_in[1];
    int N = in_sizes[0] / 2;
    int E = in_sizes[1] / 2;
    const int* src = eidx;
    const int* dst = eidx + E;
    float* out = (float*)d_out;

    cudaMemcpyToSymbolAsync(cW, d_in[2],  8 * sizeof(float),  0 * sizeof(float), cudaMemcpyDeviceToDevice, 0); // W1
    cudaMemcpyToSymbolAsync(cW, d_in[3],  4 * sizeof(float),  8 * sizeof(float), cudaMemcpyDeviceToDevice, 0); // b1
    cudaMemcpyToSymbolAsync(cW, d_in[4], 12 * sizeof(float), 12 * sizeof(float), cudaMemcpyDeviceToDevice, 0); // W2
    cudaMemcpyToSymbolAsync(cW, d_in[5],  3 * sizeof(float), 24 * sizeof(float), cudaMemcpyDeviceToDevice, 0); // b2
    cudaMemcpyToSymbolAsync(cW, d_in[6], 12 * sizeof(float), 27 * sizeof(float), cudaMemcpyDeviceToDevice, 0); // W3
    cudaMemcpyToSymbolAsync(cW, d_in[7],  4 * sizeof(float), 39 * sizeof(float), cudaMemcpyDeviceToDevice, 0); // b3
    cudaMemcpyToSymbolAsync(cW, d_in[8], 12 * sizeof(float), 43 * sizeof(float), cudaMemcpyDeviceToDevice, 0); // W4
    cudaMemcpyToSymbolAsync(cW, d_in[9],  3 * sizeof(float), 55 * sizeof(float), cudaMemcpyDeviceToDevice, 0); // b4
    cudaMemcpyToSymbolAsync(cW, d_in[10], 3 * sizeof(float), 58 * sizeof(float), cudaMemcpyDeviceToDevice, 0); // W5
    cudaMemcpyToSymbolAsync(cW, d_in[11], 1 * sizeof(float), 61 * sizeof(float), cudaMemcpyDeviceToDevice, 0); // b5

    void* degPtr = nullptr;
    cudaGetSymbolAddress(&degPtr, g_deg);
    cudaMemsetAsync(degPtr, 0, N * sizeof(int), 0);

    int nodeBlocks  = (N + NTHREADS - 1) / NTHREADS;
    int edgeBlocks8 = ((E + 7) / 8 + NTHREADS - 1) / NTHREADS;

    k_deg     <<<edgeBlocks8, NTHREADS>>>(dst, E);
    k_node1   <<<nodeBlocks, NTHREADS>>>(x, N);
    k_scatter1<<<edgeBlocks8, NTHREADS>>>(src, dst, E);
    k_node2   <<<nodeBlocks, NTHREADS>>>(N);
    k_scatter2<<<edgeBlocks8, NTHREADS>>>(src, dst, E);
    k_node3   <<<nodeBlocks, NTHREADS>>>(out, N);
}

// round 16
// speedup vs baseline: 1.4072x; 1.0727x over previous
#include <cuda_runtime.h>
#include <cuda_bf16.h>
#include <math.h>

// ---------------------------------------------------------------------------
// GCN, RED-scatter formulation (R4 structure) + L2 cache-policy hints via
// createpolicy + ld.global.nc.L2::cache_hint (works at any vector width):
//   deg -> node1 (y = dinv*x, float2) -> scatter1 (red.v2)
//       -> node2 (h1 = relu(dinv*(S@W1)+b1); featB = dinv*(h1@W2)) -> scatter2 (red.v4)
//       -> node3 (sigmoid + MLP head)
// Index streams: evict_first (don't pollute). Feature gathers: evict_last
// (pin hot arrays in L2).
// ---------------------------------------------------------------------------

#define MAX_N 1000000
#define NTHREADS 256

__device__ int    g_deg[MAX_N];
__device__ float  g_dinv[MAX_N];
__device__ float2 g_y[MAX_N];      // layer-1 gather source (dinv * x), 8B
__device__ float2 g_accA[MAX_N];   // layer-1 accumulator
__device__ float4 g_featB[MAX_N];  // layer-2 gather source (dinv * h1@W2, w=0)
__device__ float4 g_accB[MAX_N];   // layer-2 accumulator

__device__ __forceinline__ void red2(float2* p, float2 v) {
    asm volatile("red.global.add.v2.f32 [%0], {%1,%2};"
                 :: "l"(p), "f"(v.x), "f"(v.y) : "memory");
}
__device__ __forceinline__ void red4(float4* p, float4 v) {
    asm volatile("red.global.add.v4.f32 [%0], {%1,%2,%3,%4};"
                 :: "l"(p), "f"(v.x), "f"(v.y), "f"(v.z), "f"(v.w) : "memory");
}
__device__ __forceinline__ unsigned long long pol_ef() {
    unsigned long long p;
    asm("createpolicy.fractional.L2::evict_first.b64 %0, 1.0;" : "=l"(p));
    return p;
}
__device__ __forceinline__ unsigned long long pol_el() {
    unsigned long long p;
    asm("createpolicy.fractional.L2::evict_last.b64 %0, 1.0;" : "=l"(p));
    return p;
}
// streaming index load: don't displace hot L2 lines
__device__ __forceinline__ int4 ldg_ef(const int* p, unsigned long long pol) {
    int4 v;
    asm volatile("ld.global.nc.L2::cache_hint.v4.s32 {%0,%1,%2,%3}, [%4], %5;"
                 : "=r"(v.x), "=r"(v.y), "=r"(v.z), "=r"(v.w) : "l"(p), "l"(pol));
    return v;
}
// hot feature gather: keep resident in L2
__device__ __forceinline__ float2 ldg_el2(const float2* p, unsigned long long pol) {
    float2 v;
    asm volatile("ld.global.nc.L2::cache_hint.v2.f32 {%0,%1}, [%2], %3;"
                 : "=f"(v.x), "=f"(v.y) : "l"(p), "l"(pol));
    return v;
}
__device__ __forceinline__ float4 ldg_el4(const float4* p, unsigned long long pol) {
    float4 v;
    asm volatile("ld.global.nc.L2::cache_hint.v4.f32 {%0,%1,%2,%3}, [%4], %5;"
                 : "=f"(v.x), "=f"(v.y), "=f"(v.z), "=f"(v.w) : "l"(p), "l"(pol));
    return v;
}

// ---- degree count ----
__global__ void k_deg(const int* __restrict__ dst, int E) {
    unsigned long long pef = pol_ef();
    int i = (blockIdx.x * blockDim.x + threadIdx.x) * 4;
    if (i + 3 < E) {
        int4 d = ldg_ef(dst + i, pef);
        atomicAdd(&g_deg[d.x], 1);
        atomicAdd(&g_deg[d.y], 1);
        atomicAdd(&g_deg[d.z], 1);
        atomicAdd(&g_deg[d.w], 1);
    } else {
        for (int j = i; j < E; j++) atomicAdd(&g_deg[dst[j]], 1);
    }
}

// ---- node pass 1: dinv, y = dinv * x, accA = y (self loop) ----
__global__ void k_node1(const float* __restrict__ x, int N) {
    int i = blockIdx.x * blockDim.x + threadIdx.x;
    if (i >= N) return;
    float dinv = rsqrtf((float)(g_deg[i] + 1));
    float2 xv = ((const float2*)x)[i];
    float2 y;
    y.x = dinv * xv.x;
    y.y = dinv * xv.y;
    g_dinv[i] = dinv;
    g_y[i]    = y;
    g_accA[i] = y;
}

// ---- scatter layer 1: accA[dst] += y[src]  (red.v2) ----
__global__ void k_scatter1(const int* __restrict__ src, const int* __restrict__ dst, int E) {
    unsigned long long pef = pol_ef();
    unsigned long long pel = pol_el();
    int i = (blockIdx.x * blockDim.x + threadIdx.x) * 4;
    if (i + 3 < E) {
        int4 s = ldg_ef(src + i, pef);
        int4 d = ldg_ef(dst + i, pef);
        float2 a0 = ldg_el2(&g_y[s.x], pel);
        float2 a1 = ldg_el2(&g_y[s.y], pel);
        float2 a2 = ldg_el2(&g_y[s.z], pel);
        float2 a3 = ldg_el2(&g_y[s.w], pel);
        red2(&g_accA[d.x], a0);
        red2(&g_accA[d.y], a1);
        red2(&g_accA[d.z], a2);
        red2(&g_accA[d.w], a3);
    } else {
        for (int j = i; j < E; j++) red2(&g_accA[dst[j]], g_y[src[j]]);
    }
}

// ---- node pass 2: h1 = relu(dinv*(S@W1)+b1); featB = dinv*(h1@W2); accB = featB ----
__global__ void k_node2(const float* __restrict__ W1, const float* __restrict__ b1,
                        const float* __restrict__ W2, int N) {
    int i = blockIdx.x * blockDim.x + threadIdx.x;
    if (i >= N) return;
    float dinv = g_dinv[i];
    float2 S = g_accA[i];
    // h1 = relu(dinv*(S@W1) + b1); W1 [2,4] row-major
    float h0 = fmaxf(dinv * (S.x * __ldg(W1+0) + S.y * __ldg(W1+4)) + __ldg(b1+0), 0.f);
    float h1 = fmaxf(dinv * (S.x * __ldg(W1+1) + S.y * __ldg(W1+5)) + __ldg(b1+1), 0.f);
    float h2 = fmaxf(dinv * (S.x * __ldg(W1+2) + S.y * __ldg(W1+6)) + __ldg(b1+2), 0.f);
    float h3 = fmaxf(dinv * (S.x * __ldg(W1+3) + S.y * __ldg(W1+7)) + __ldg(b1+3), 0.f);
    // featB = dinv*(h1@W2); W2 [4,3] row-major
    float4 g;
    g.x = dinv * (h0*__ldg(W2+0) + h1*__ldg(W2+3) + h2*__ldg(W2+6) + h3*__ldg(W2+9));
    g.y = dinv * (h0*__ldg(W2+1) + h1*__ldg(W2+4) + h2*__ldg(W2+7) + h3*__ldg(W2+10));
    g.z = dinv * (h0*__ldg(W2+2) + h1*__ldg(W2+5) + h2*__ldg(W2+8) + h3*__ldg(W2+11));
    g.w = 0.f;
    g_featB[i] = g;
    g_accB[i]  = g;
}

// ---- scatter layer 2: accB[dst] += featB[src]  (red.v4) ----
__global__ void k_scatter2(const int* __restrict__ src, const int* __restrict__ dst, int E) {
    unsigned long long pef = pol_ef();
    unsigned long long pel = pol_el();
    int i = (blockIdx.x * blockDim.x + threadIdx.x) * 4;
    if (i + 3 < E) {
        int4 s = ldg_ef(src + i, pef);
        int4 d = ldg_ef(dst + i, pef);
        float4 a0 = ldg_el4(&g_featB[s.x], pel);
        float4 a1 = ldg_el4(&g_featB[s.y], pel);
        float4 a2 = ldg_el4(&g_featB[s.z], pel);
        float4 a3 = ldg_el4(&g_featB[s.w], pel);
        red4(&g_accB[d.x], a0);
        red4(&g_accB[d.y], a1);
        red4(&g_accB[d.z], a2);
        red4(&g_accB[d.w], a3);
    } else {
        for (int j = i; j < E; j++) red4(&g_accB[dst[j]], g_featB[src[j]]);
    }
}

// ---- node pass 3: sigmoid + MLP head ----
__global__ void k_node3(const float* __restrict__ b2,
                        const float* __restrict__ W3, const float* __restrict__ b3,
                        const float* __restrict__ W4, const float* __restrict__ b4,
                        const float* __restrict__ W5, const float* __restrict__ b5,
                        float* __restrict__ out, int N) {
    int i = blockIdx.x * blockDim.x + threadIdx.x;
    if (i >= N) return;
    float dinv = g_dinv[i];
    float4 a = g_accB[i];
    float q0 = 1.f / (1.f + expf(-(a.x * dinv + __ldg(b2+0))));
    float q1 = 1.f / (1.f + expf(-(a.y * dinv + __ldg(b2+1))));
    float q2 = 1.f / (1.f + expf(-(a.z * dinv + __ldg(b2+2))));
    // h3 = relu(q @ W3[3,4] + b3)
    float u0 = fmaxf(q0*__ldg(W3+0) + q1*__ldg(W3+4) + q2*__ldg(W3+8)  + __ldg(b3+0), 0.f);
    float u1 = fmaxf(q0*__ldg(W3+1) + q1*__ldg(W3+5) + q2*__ldg(W3+9)  + __ldg(b3+1), 0.f);
    float u2 = fmaxf(q0*__ldg(W3+2) + q1*__ldg(W3+6) + q2*__ldg(W3+10) + __ldg(b3+2), 0.f);
    float u3 = fmaxf(q0*__ldg(W3+3) + q1*__ldg(W3+7) + q2*__ldg(W3+11) + __ldg(b3+3), 0.f);
    // h4 = relu(u @ W4[4,3] + b4)
    float v0 = fmaxf(u0*__ldg(W4+0) + u1*__ldg(W4+3) + u2*__ldg(W4+6) + u3*__ldg(W4+9)  + __ldg(b4+0), 0.f);
    float v1 = fmaxf(u0*__ldg(W4+1) + u1*__ldg(W4+4) + u2*__ldg(W4+7) + u3*__ldg(W4+10) + __ldg(b4+1), 0.f);
    float v2 = fmaxf(u0*__ldg(W4+2) + u1*__ldg(W4+5) + u2*__ldg(W4+8) + u3*__ldg(W4+11) + __ldg(b4+2), 0.f);
    out[i] = v0*__ldg(W5+0) + v1*__ldg(W5+1) + v2*__ldg(W5+2) + __ldg(b5+0);
}

extern "C" void kernel_launch(void* const* d_in, const int* in_sizes, int n_in,
                              void* d_out, int out_size) {
    const float* x    = (const float*)d_in[0];
    const int*   eidx = (const int*)d_in[1];
    int N = in_sizes[0] / 2;
    int E = in_sizes[1] / 2;
    const int* src = eidx;
    const int* dst = eidx + E;
    float* out = (float*)d_out;

    const float* W1 = (const float*)d_in[2];
    const float* b1 = (const float*)d_in[3];
    const float* W2 = (const float*)d_in[4];
    const float* b2 = (const float*)d_in[5];
    const float* W3 = (const float*)d_in[6];
    const float* b3 = (const float*)d_in[7];
    const float* W4 = (const float*)d_in[8];
    const float* b4 = (const float*)d_in[9];
    const float* W5 = (const float*)d_in[10];
    const float* b5 = (const float*)d_in[11];

    void* degPtr = nullptr;
    cudaGetSymbolAddress(&degPtr, g_deg);
    cudaMemsetAsync(degPtr, 0, N * sizeof(int), 0);

    int nodeBlocks = (N + NTHREADS - 1) / NTHREADS;
    int edgeBlocks = ((E + 3) / 4 + NTHREADS - 1) / NTHREADS;

    k_deg     <<<edgeBlocks, NTHREADS>>>(dst, E);
    k_node1   <<<nodeBlocks, NTHREADS>>>(x, N);
    k_scatter1<<<edgeBlocks, NTHREADS>>>(src, dst, E);
    k_node2   <<<nodeBlocks, NTHREADS>>>(W1, b1, W2, N);
    k_scatter2<<<edgeBlocks, NTHREADS>>>(src, dst, E);
    k_node3   <<<nodeBlocks, NTHREADS>>>(b2, W3, b3, W4, b4, W5, b5, out, N);
}